// round 5
// baseline (speedup 1.0000x reference)
#include <cuda_runtime.h>

#define T_LEN 200
#define B_SZ  1024
#define D_SZ  128
#define G3    384
#define RB    8
#define WSTR  132   // weight row stride (floats): 132*4B, conflict-free LDS.128

// Precomputed x-side: [T*B][384] = (xWau+bau | xWar+bar | xWac+bac)
__device__ float g_X[(size_t)T_LEN * B_SZ * G3];

// ---------- packed fp32 helpers (Blackwell f32x2) ----------
__device__ __forceinline__ void fma2(unsigned long long &d,
                                     unsigned long long a,
                                     unsigned long long b) {
    asm("fma.rn.f32x2 %0, %1, %2, %0;" : "+l"(d) : "l"(a), "l"(b));
}
__device__ __forceinline__ unsigned long long pack2(float x, float y) {
    unsigned long long r;
    asm("mov.b64 %0, {%1, %2};" : "=l"(r) : "f"(x), "f"(y));
    return r;
}
__device__ __forceinline__ void unpack2(unsigned long long v, float &lo, float &hi) {
    asm("mov.b64 {%0, %1}, %2;" : "=f"(lo), "=f"(hi) : "l"(v));
}
__device__ __forceinline__ float sum2(unsigned long long v) {
    float lo, hi; unpack2(v, lo, hi); return lo + hi;
}

// =====================================================================
// Kernel 1: X-side GEMM (UNCHANGED from the passing R4 kernel).
// =====================================================================
#define TM 64
#define TN 64
#define TK 64
#define ASTR 68
#define BSTR 68

__global__ __launch_bounds__(256) void gemm_x(
    const float* __restrict__ Xin,
    const float* __restrict__ Wau, const float* __restrict__ bau,
    const float* __restrict__ War, const float* __restrict__ bar,
    const float* __restrict__ Wac, const float* __restrict__ bac)
{
    __shared__ float As[TM * ASTR];
    __shared__ float Bs[TK * BSTR];

    const int tid = threadIdx.x;
    const int tx = tid & 15;
    const int ty = tid >> 4;
    const int m0 = blockIdx.x * TM;
    const int n0 = blockIdx.y * TN;
    const int gate = n0 >> 7;
    const int cg = n0 & 127;

    const float* W    = (gate == 0) ? Wau : ((gate == 1) ? War : Wac);
    const float* bias = (gate == 0) ? bau : ((gate == 1) ? bar : bac);

    unsigned long long acc[4][2];
    #pragma unroll
    for (int i = 0; i < 4; i++) { acc[i][0] = 0ULL; acc[i][1] = 0ULL; }

    for (int k0 = 0; k0 < D_SZ; k0 += TK) {
        #pragma unroll
        for (int l = 0; l < 4; l++) {
            int idx = tid + l * 256;
            int row = idx >> 4;
            int c4  = idx & 15;
            float4 av = *(const float4*)(Xin + (size_t)(m0 + row) * D_SZ + k0 + c4 * 4);
            *(float4*)(As + row * ASTR + c4 * 4) = av;
            float4 bv = *(const float4*)(W + (size_t)(k0 + row) * D_SZ + cg + c4 * 4);
            *(float4*)(Bs + row * BSTR + c4 * 4) = bv;
        }
        __syncthreads();

        #pragma unroll 16
        for (int kk = 0; kk < TK; kk++) {
            unsigned long long b0 = *(const unsigned long long*)(Bs + kk * BSTR + tx * 4);
            unsigned long long b1 = *(const unsigned long long*)(Bs + kk * BSTR + tx * 4 + 2);
            #pragma unroll
            for (int i = 0; i < 4; i++) {
                float a = As[(ty * 4 + i) * ASTR + kk];
                unsigned long long a2 = pack2(a, a);
                fma2(acc[i][0], a2, b0);
                fma2(acc[i][1], a2, b1);
            }
        }
        __syncthreads();
    }

    float b0f = bias[cg + tx * 4 + 0];
    float b1f = bias[cg + tx * 4 + 1];
    float b2f = bias[cg + tx * 4 + 2];
    float b3f = bias[cg + tx * 4 + 3];
    #pragma unroll
    for (int i = 0; i < 4; i++) {
        int m = m0 + ty * 4 + i;
        float v0, v1, v2, v3;
        unpack2(acc[i][0], v0, v1);
        unpack2(acc[i][1], v2, v3);
        float4 o = make_float4(v0 + b0f, v1 + b1f, v2 + b2f, v3 + b3f);
        *(float4*)(g_X + (size_t)m * G3 + n0 + tx * 4) = o;
    }
}

// =====================================================================
// Kernel 2: recurrence, K-split version.
// 128 blocks x 8 batch rows, 256 threads.
//   half = tid>>7 (0: k in [0,64), 1: k in [64,128)), d = tid&127.
// Each thread accumulates partial dots for ALL 8 rows x 3 gates over its
// half of k, exchanges pre-reduced partials through smem, then computes
// gates for its 4 owned rows (half*4 .. half*4+3).
// Weights transposed in smem [384][132] -> conflict-free LDS.128.
// =====================================================================
extern __shared__ float smem_rec[];

__global__ __launch_bounds__(256, 1) void augru_rec(
    const float* __restrict__ state, const float* __restrict__ att,
    const float* __restrict__ mask,
    const float* __restrict__ Wbu, const float* __restrict__ Wbr,
    const float* __restrict__ Wbc,
    float* __restrict__ out)
{
    float* WsT  = smem_rec;                          // [384][132]
    float* sb   = smem_rec + G3 * WSTR;              // [2][8][128]
    float* part = sb + 2 * RB * 128;                 // [2][3][4][128]
    const int tid  = threadIdx.x;
    const int half = tid >> 7;
    const int d    = tid & 127;
    const int b0   = blockIdx.x * RB;

    // Transposed weight load: coalesced gmem reads.
    #pragma unroll
    for (int g = 0; g < 3; g++) {
        const float* W = (g == 0) ? Wbu : ((g == 1) ? Wbr : Wbc);
        for (int i = tid; i < D_SZ * D_SZ; i += 256) {
            int k = i >> 7;
            int n = i & 127;
            WsT[(g * 128 + n) * WSTR + k] = W[i];
        }
    }

    // Initial state: each half loads/keeps its 4 owned rows.
    float s_reg[4];
    #pragma unroll
    for (int rr = 0; rr < 4; rr++) {
        int ro = half * 4 + rr;
        s_reg[rr] = state[(size_t)(b0 + ro) * D_SZ + d];
        sb[ro * 128 + d] = s_reg[rr];
    }
    __syncthreads();

    const int k0 = half * 64;
    const float* wu = WsT + (size_t)d * WSTR + k0;
    const float* wr = WsT + (size_t)(128 + d) * WSTR + k0;
    const float* wc = WsT + (size_t)(256 + d) * WSTR + k0;

    int cur = 0;
    for (int t = 0; t < T_LEN; t++) {
        // Prefetch x-side + att/mask for owned rows (consumed ~3k cyc later).
        const float* Xt = g_X + ((size_t)t * B_SZ + b0) * G3;
        float xu[4], xr[4], xc[4], am[4], mm[4];
        #pragma unroll
        for (int rr = 0; rr < 4; rr++) {
            int ro = half * 4 + rr;
            xu[rr] = Xt[ro * G3 + d];
            xr[rr] = Xt[ro * G3 + 128 + d];
            xc[rr] = Xt[ro * G3 + 256 + d];
            am[rr] = __ldg(att + (size_t)t * B_SZ + b0 + ro);
            mm[rr] = __ldg(mask + (size_t)(b0 + ro) * T_LEN + t);
        }

        unsigned long long au[RB], ar[RB], ac[RB];
        #pragma unroll
        for (int r = 0; r < RB; r++) { au[r] = 0ULL; ar[r] = 0ULL; ac[r] = 0ULL; }

        const float* srow = sb + cur * (RB * 128) + k0;
        #pragma unroll 4
        for (int k4 = 0; k4 < 16; k4++) {
            ulonglong2 w_u = *(const ulonglong2*)(wu + 4 * k4);
            ulonglong2 w_r = *(const ulonglong2*)(wr + 4 * k4);
            ulonglong2 w_c = *(const ulonglong2*)(wc + 4 * k4);
            #pragma unroll
            for (int r = 0; r < RB; r++) {
                ulonglong2 s2 = *(const ulonglong2*)(srow + r * 128 + 4 * k4);
                fma2(au[r], w_u.x, s2.x);
                fma2(au[r], w_u.y, s2.y);
                fma2(ar[r], w_r.x, s2.x);
                fma2(ar[r], w_r.y, s2.y);
                fma2(ac[r], w_c.x, s2.x);
                fma2(ac[r], w_c.y, s2.y);
            }
        }

        // Exchange: store pre-reduced partials for the 4 FOREIGN rows.
        // Producer region 'half': rows owned by the other half.
        {
            int fbase = (half ^ 1) * 4;   // foreign row base
            float* pdst = part + (size_t)half * (3 * 4 * 128);
            #pragma unroll
            for (int rr = 0; rr < 4; rr++) {
                pdst[(0 * 4 + rr) * 128 + d] = sum2(au[fbase + rr]);
                pdst[(1 * 4 + rr) * 128 + d] = sum2(ar[fbase + rr]);
                pdst[(2 * 4 + rr) * 128 + d] = sum2(ac[fbase + rr]);
            }
        }
        __syncthreads();

        // Gates for owned rows: own partial + partner partial.
        const int nxt = cur ^ 1;
        float* dst = sb + nxt * (RB * 128);
        const float* psrc = part + (size_t)(half ^ 1) * (3 * 4 * 128);
        #pragma unroll
        for (int rr = 0; rr < 4; rr++) {
            int ro = half * 4 + rr;
            float hu = xu[rr] + sum2(au[ro]) + psrc[(0 * 4 + rr) * 128 + d];
            float hr = xr[rr] + sum2(ar[ro]) + psrc[(1 * 4 + rr) * 128 + d];
            float dc =          sum2(ac[ro]) + psrc[(2 * 4 + rr) * 128 + d];
            float ug = __fdividef(1.0f, 1.0f + __expf(-hu));
            float rg = __fdividef(1.0f, 1.0f + __expf(-hr));
            float hc = xc[rr] + rg * dc;
            float e2 = __expf(2.0f * hc);
            float cd = 1.0f - __fdividef(2.0f, e2 + 1.0f);   // tanh(hc)
            float ua = am[rr] * ug;
            float sn = s_reg[rr] + mm[rr] * ua * (cd - s_reg[rr]);
            s_reg[rr] = sn;
            dst[ro * 128 + d] = sn;
        }
        cur = nxt;
        __syncthreads();
    }

    #pragma unroll
    for (int rr = 0; rr < 4; rr++) {
        int ro = half * 4 + rr;
        out[(size_t)(b0 + ro) * D_SZ + d] = s_reg[rr];
    }
}

// =====================================================================
extern "C" void kernel_launch(void* const* d_in, const int* in_sizes, int n_in,
                              void* d_out, int out_size)
{
    const float* inputs = (const float*)d_in[0];
    const float* state  = (const float*)d_in[1];
    const float* att    = (const float*)d_in[2];
    const float* mask   = (const float*)d_in[3];
    int w = (n_in >= 14) ? 5 : 4;
    const float* Wau = (const float*)d_in[w + 0];
    const float* bau = (const float*)d_in[w + 1];
    const float* Wbu = (const float*)d_in[w + 2];
    const float* War = (const float*)d_in[w + 3];
    const float* bar = (const float*)d_in[w + 4];
    const float* Wbr = (const float*)d_in[w + 5];
    const float* Wac = (const float*)d_in[w + 6];
    const float* bac = (const float*)d_in[w + 7];
    const float* Wbc = (const float*)d_in[w + 8];
    float* out = (float*)d_out;
    (void)in_sizes; (void)out_size;

    dim3 g1(T_LEN * B_SZ / TM, G3 / TN);   // (3200, 6)
    gemm_x<<<g1, 256>>>(inputs, Wau, bau, War, bar, Wac, bac);

    // smem: weights 384*132 + state 2*8*128 + partials 2*3*4*128 floats
    size_t smem = (size_t)(G3 * WSTR + 2 * RB * 128 + 2 * 3 * 4 * 128)
                  * sizeof(float);          // 223,232 B
    cudaFuncSetAttribute(augru_rec, cudaFuncAttributeMaxDynamicSharedMemorySize,
                         (int)smem);
    augru_rec<<<B_SZ / RB, 256, smem>>>(state, att, mask, Wbu, Wbr, Wbc, out);
}

// round 6
// speedup vs baseline: 1.3465x; 1.3465x over previous
#include <cuda_runtime.h>

#define T_LEN 200
#define B_SZ  1024
#define D_SZ  128
#define G3    384
#define RB    8
#define WSTR  132   // weight row stride (floats) -> conflict-free LDS.128

// Precomputed x-side: [T*B][384] = (xWau+bau | xWar+bar | xWac+bac)
__device__ float g_X[(size_t)T_LEN * B_SZ * G3];

// ---------- packed fp32 helpers (Blackwell f32x2) ----------
__device__ __forceinline__ void fma2(unsigned long long &d,
                                     unsigned long long a,
                                     unsigned long long b) {
    asm("fma.rn.f32x2 %0, %1, %2, %0;" : "+l"(d) : "l"(a), "l"(b));
}
__device__ __forceinline__ unsigned long long pack2(float x, float y) {
    unsigned long long r;
    asm("mov.b64 %0, {%1, %2};" : "=l"(r) : "f"(x), "f"(y));
    return r;
}
__device__ __forceinline__ void unpack2(unsigned long long v, float &lo, float &hi) {
    asm("mov.b64 {%0, %1}, %2;" : "=f"(lo), "=f"(hi) : "l"(v));
}
__device__ __forceinline__ float sum2(unsigned long long v) {
    float lo, hi; unpack2(v, lo, hi); return lo + hi;
}

// =====================================================================
// Kernel 1: X-side GEMM (UNCHANGED from the passing R4 kernel).
// =====================================================================
#define TM 64
#define TN 64
#define TK 64
#define ASTR 68
#define BSTR 68

__global__ __launch_bounds__(256) void gemm_x(
    const float* __restrict__ Xin,
    const float* __restrict__ Wau, const float* __restrict__ bau,
    const float* __restrict__ War, const float* __restrict__ bar,
    const float* __restrict__ Wac, const float* __restrict__ bac)
{
    __shared__ float As[TM * ASTR];
    __shared__ float Bs[TK * BSTR];

    const int tid = threadIdx.x;
    const int tx = tid & 15;
    const int ty = tid >> 4;
    const int m0 = blockIdx.x * TM;
    const int n0 = blockIdx.y * TN;
    const int gate = n0 >> 7;
    const int cg = n0 & 127;

    const float* W    = (gate == 0) ? Wau : ((gate == 1) ? War : Wac);
    const float* bias = (gate == 0) ? bau : ((gate == 1) ? bar : bac);

    unsigned long long acc[4][2];
    #pragma unroll
    for (int i = 0; i < 4; i++) { acc[i][0] = 0ULL; acc[i][1] = 0ULL; }

    for (int k0 = 0; k0 < D_SZ; k0 += TK) {
        #pragma unroll
        for (int l = 0; l < 4; l++) {
            int idx = tid + l * 256;
            int row = idx >> 4;
            int c4  = idx & 15;
            float4 av = *(const float4*)(Xin + (size_t)(m0 + row) * D_SZ + k0 + c4 * 4);
            *(float4*)(As + row * ASTR + c4 * 4) = av;
            float4 bv = *(const float4*)(W + (size_t)(k0 + row) * D_SZ + cg + c4 * 4);
            *(float4*)(Bs + row * BSTR + c4 * 4) = bv;
        }
        __syncthreads();

        #pragma unroll 16
        for (int kk = 0; kk < TK; kk++) {
            unsigned long long b0 = *(const unsigned long long*)(Bs + kk * BSTR + tx * 4);
            unsigned long long b1 = *(const unsigned long long*)(Bs + kk * BSTR + tx * 4 + 2);
            #pragma unroll
            for (int i = 0; i < 4; i++) {
                float a = As[(ty * 4 + i) * ASTR + kk];
                unsigned long long a2 = pack2(a, a);
                fma2(acc[i][0], a2, b0);
                fma2(acc[i][1], a2, b1);
            }
        }
        __syncthreads();
    }

    float b0f = bias[cg + tx * 4 + 0];
    float b1f = bias[cg + tx * 4 + 1];
    float b2f = bias[cg + tx * 4 + 2];
    float b3f = bias[cg + tx * 4 + 3];
    #pragma unroll
    for (int i = 0; i < 4; i++) {
        int m = m0 + ty * 4 + i;
        float v0, v1, v2, v3;
        unpack2(acc[i][0], v0, v1);
        unpack2(acc[i][1], v2, v3);
        float4 o = make_float4(v0 + b0f, v1 + b1f, v2 + b2f, v3 + b3f);
        *(float4*)(g_X + (size_t)m * G3 + n0 + tx * 4) = o;
    }
}

// =====================================================================
// Kernel 2: recurrence. 128 blocks x 8 rows, 256 threads, NO exchange.
//   rg = tid>>7 owns rows rg*4..rg*4+3 (FULL K per thread), d = tid&127.
// 2 warps/SMSP for latency hiding; one __syncthreads per step.
// Weights transposed in smem [384][132] -> conflict-free LDS.128.
// State double-buffered in smem.
// =====================================================================
extern __shared__ float smem_rec[];

__global__ __launch_bounds__(256, 1) void augru_rec(
    const float* __restrict__ state, const float* __restrict__ att,
    const float* __restrict__ mask,
    const float* __restrict__ Wbu, const float* __restrict__ Wbr,
    const float* __restrict__ Wbc,
    float* __restrict__ out)
{
    float* WsT = smem_rec;                       // [384][132]
    float* sb  = smem_rec + G3 * WSTR;           // [2][8][128]
    const int tid = threadIdx.x;
    const int rg  = tid >> 7;                    // row group: 0 -> rows 0-3, 1 -> rows 4-7
    const int d   = tid & 127;
    const int b0  = blockIdx.x * RB;

    // Transposed weight load: coalesced gmem reads.
    #pragma unroll
    for (int g = 0; g < 3; g++) {
        const float* W = (g == 0) ? Wbu : ((g == 1) ? Wbr : Wbc);
        for (int i = tid; i < D_SZ * D_SZ; i += 256) {
            int k = i >> 7;
            int n = i & 127;
            WsT[(g * 128 + n) * WSTR + k] = W[i];
        }
    }

    float s_reg[4];
    #pragma unroll
    for (int rr = 0; rr < 4; rr++) {
        int ro = rg * 4 + rr;
        s_reg[rr] = state[(size_t)(b0 + ro) * D_SZ + d];
        sb[ro * 128 + d] = s_reg[rr];
    }
    __syncthreads();

    const float* wu = WsT + (size_t)d * WSTR;
    const float* wr = WsT + (size_t)(128 + d) * WSTR;
    const float* wc = WsT + (size_t)(256 + d) * WSTR;

    int cur = 0;
    for (int t = 0; t < T_LEN; t++) {
        // Prefetch x-side + att/mask for owned rows; consumed after the
        // ~4k-cycle dot loop -> DRAM latency fully hidden.
        const float* Xt = g_X + ((size_t)t * B_SZ + b0) * G3;
        float xu[4], xr[4], xc[4], am[4], mm[4];
        #pragma unroll
        for (int rr = 0; rr < 4; rr++) {
            int ro = rg * 4 + rr;
            xu[rr] = Xt[ro * G3 + d];
            xr[rr] = Xt[ro * G3 + 128 + d];
            xc[rr] = Xt[ro * G3 + 256 + d];
            am[rr] = __ldg(att + (size_t)t * B_SZ + b0 + ro);
            mm[rr] = __ldg(mask + (size_t)(b0 + ro) * T_LEN + t);
        }

        unsigned long long au[4], ar[4], ac[4];
        #pragma unroll
        for (int rr = 0; rr < 4; rr++) { au[rr] = 0ULL; ar[rr] = 0ULL; ac[rr] = 0ULL; }

        const float* srow = sb + cur * (RB * 128) + rg * 4 * 128;
        #pragma unroll 8
        for (int k4 = 0; k4 < 32; k4++) {
            ulonglong2 w_u = *(const ulonglong2*)(wu + 4 * k4);
            ulonglong2 w_r = *(const ulonglong2*)(wr + 4 * k4);
            ulonglong2 w_c = *(const ulonglong2*)(wc + 4 * k4);
            #pragma unroll
            for (int rr = 0; rr < 4; rr++) {
                ulonglong2 s2 = *(const ulonglong2*)(srow + rr * 128 + 4 * k4);
                fma2(au[rr], w_u.x, s2.x);
                fma2(au[rr], w_u.y, s2.y);
                fma2(ar[rr], w_r.x, s2.x);
                fma2(ar[rr], w_r.y, s2.y);
                fma2(ac[rr], w_c.x, s2.x);
                fma2(ac[rr], w_c.y, s2.y);
            }
        }

        const int nxt = cur ^ 1;
        float* dst = sb + nxt * (RB * 128);
        #pragma unroll
        for (int rr = 0; rr < 4; rr++) {
            int ro = rg * 4 + rr;
            float hu = xu[rr] + sum2(au[rr]);
            float hr = xr[rr] + sum2(ar[rr]);
            float dc = sum2(ac[rr]);
            float ug = __fdividef(1.0f, 1.0f + __expf(-hu));
            float rg_ = __fdividef(1.0f, 1.0f + __expf(-hr));
            float hc = xc[rr] + rg_ * dc;
            float e2 = __expf(2.0f * hc);
            float cd = 1.0f - __fdividef(2.0f, e2 + 1.0f);   // tanh(hc)
            float ua = am[rr] * ug;
            float sn = s_reg[rr] + mm[rr] * ua * (cd - s_reg[rr]);
            s_reg[rr] = sn;
            dst[ro * 128 + d] = sn;
        }
        cur = nxt;
        __syncthreads();
    }

    #pragma unroll
    for (int rr = 0; rr < 4; rr++) {
        int ro = rg * 4 + rr;
        out[(size_t)(b0 + ro) * D_SZ + d] = s_reg[rr];
    }
}

// =====================================================================
extern "C" void kernel_launch(void* const* d_in, const int* in_sizes, int n_in,
                              void* d_out, int out_size)
{
    const float* inputs = (const float*)d_in[0];
    const float* state  = (const float*)d_in[1];
    const float* att    = (const float*)d_in[2];
    const float* mask   = (const float*)d_in[3];
    int w = (n_in >= 14) ? 5 : 4;
    const float* Wau = (const float*)d_in[w + 0];
    const float* bau = (const float*)d_in[w + 1];
    const float* Wbu = (const float*)d_in[w + 2];
    const float* War = (const float*)d_in[w + 3];
    const float* bar = (const float*)d_in[w + 4];
    const float* Wbr = (const float*)d_in[w + 5];
    const float* Wac = (const float*)d_in[w + 6];
    const float* bac = (const float*)d_in[w + 7];
    const float* Wbc = (const float*)d_in[w + 8];
    float* out = (float*)d_out;
    (void)in_sizes; (void)out_size;

    dim3 g1(T_LEN * B_SZ / TM, G3 / TN);   // (3200, 6)
    gemm_x<<<g1, 256>>>(inputs, Wau, bau, War, bar, Wac, bac);

    // smem: weights 384*132 + state 2*8*128 floats = 210,944 B
    size_t smem = (size_t)(G3 * WSTR + 2 * RB * 128) * sizeof(float);
    cudaFuncSetAttribute(augru_rec, cudaFuncAttributeMaxDynamicSharedMemorySize,
                         (int)smem);
    augru_rec<<<B_SZ / RB, 256, smem>>>(state, att, mask, Wbu, Wbr, Wbc, out);
}